// round 11
// baseline (speedup 1.0000x reference)
#include <cuda_runtime.h>
#include <cstdint>

#define B_    32
#define CIN   256
#define COUT  512
#define HIN   56
#define WIN   56
#define HOUT  54
#define WOUT  54
#define HWOUT (HOUT * WOUT)          // 2916 = 729 * 4
#define EPS   1e-5f
#define DW_THRESH 4.0f
#define PW_THRESH 0.001f

// Scratch (device globals: the only allowed scratch mechanism).
__device__ float g_y[(size_t)B_ * CIN * HWOUT];   // depthwise output, written only for survivors
__device__ int   g_flag[B_ * CIN];                // per-(b,c) survival flag (rewritten every run)
__device__ int   g_done[B_];                      // dw blocks completed per batch (self-resetting)
__device__ int   g_batchdone;                     // batches fully done (self-resetting)

__device__ __forceinline__ float block_max_256(float v) {
    __shared__ float s_red[8];
    #pragma unroll
    for (int off = 16; off > 0; off >>= 1)
        v = fmaxf(v, __shfl_down_sync(0xffffffffu, v, off));
    if ((threadIdx.x & 31) == 0) s_red[threadIdx.x >> 5] = v;
    __syncthreads();
    if (threadIdx.x < 8) {
        v = s_red[threadIdx.x];
        #pragma unroll
        for (int off = 4; off > 0; off >>= 1)
            v = fmaxf(v, __shfl_down_sync(0xffu, v, off));
        if (threadIdx.x == 0) s_red[0] = v;
    }
    __syncthreads();
    float r = s_red[0];
    __syncthreads();
    return r;
}

// ---------------------------------------------------------------------------
// Rare-path repair, executed by the single globally-last block: recompute the
// pointwise result for every batch that had dw survivors. Slow but correct.
// ---------------------------------------------------------------------------
__device__ __noinline__
void repair_all(const float* __restrict__ pw_w,
                const float* __restrict__ pw_b,
                const float* __restrict__ pw_gamma,
                const float* __restrict__ pw_beta,
                const float* __restrict__ pw_mean,
                const float* __restrict__ pw_var,
                float* __restrict__ out)
{
    const int tid = threadIdx.x;
    __shared__ float wrow[CIN];
    __shared__ char  fl[CIN];

    for (int bi = 0; bi < B_; bi++) {
        const int myflag = g_flag[bi * CIN + tid];
        const int any = __syncthreads_or(myflag);
        if (!any) continue;                // common case for each batch

        fl[tid] = (char)(myflag != 0);

        for (int o = 0; o < COUT; o++) {
            __syncthreads();
            wrow[tid] = pw_w[(size_t)o * CIN + tid];
            __syncthreads();

            float4 acc[3];
            #pragma unroll
            for (int r = 0; r < 3; r++) acc[r] = make_float4(0.f, 0.f, 0.f, 0.f);

            for (int k = 0; k < CIN; k++) {
                if (!fl[k]) continue;
                const float wv = wrow[k];
                const float4* yr4 = (const float4*)(g_y + ((size_t)bi * CIN + k) * HWOUT);
                #pragma unroll
                for (int r = 0; r < 3; r++) {
                    const int idx = tid + r * 256;
                    if (idx < HWOUT / 4) {
                        const float4 yv = yr4[idx];
                        acc[r].x = fmaf(yv.x, wv, acc[r].x);
                        acc[r].y = fmaf(yv.y, wv, acc[r].y);
                        acc[r].z = fmaf(yv.z, wv, acc[r].z);
                        acc[r].w = fmaf(yv.w, wv, acc[r].w);
                    }
                }
            }

            const float scale = pw_gamma[o] * rsqrtf(pw_var[o] + EPS);
            const float shift = pw_beta[o] - pw_mean[o] * scale;
            const float bias  = pw_b[o];

            float4 z[3];
            float mx = 0.0f;
            #pragma unroll
            for (int r = 0; r < 3; r++) {
                z[r].x = fmaxf(fmaf(acc[r].x + bias, scale, shift), 0.0f);
                z[r].y = fmaxf(fmaf(acc[r].y + bias, scale, shift), 0.0f);
                z[r].z = fmaxf(fmaf(acc[r].z + bias, scale, shift), 0.0f);
                z[r].w = fmaxf(fmaf(acc[r].w + bias, scale, shift), 0.0f);
                mx = fmaxf(mx, fmaxf(fmaxf(z[r].x, z[r].y), fmaxf(z[r].z, z[r].w)));
            }

            const float bmax = block_max_256(mx);
            const bool cut = (bmax < PW_THRESH);

            float4* op4 = (float4*)(out + ((size_t)bi * COUT + o) * HWOUT);
            #pragma unroll
            for (int r = 0; r < 3; r++) {
                const int idx = tid + r * 256;
                if (idx < HWOUT / 4)
                    op4[idx] = cut ? make_float4(0.f, 0.f, 0.f, 0.f) : z[r];
            }
        }
    }
}

// ---------------------------------------------------------------------------
// Single fused kernel: 8192 blocks; block (b,c):
//   (0) prefetch first two conv input rows into registers
//   (1) speculative pw streaming stores for output maps (b,2c), (b,2c+1)
//   (2) depthwise 3x3 VALID + bias + BN + ReLU + map-max + cut flag for (b,c)
//   (3) release counting; the globally-last block scans flags, repairs any
//       survivor batches inline, and resets the counters for the next replay.
// ---------------------------------------------------------------------------
__global__ __launch_bounds__(256)
void fused_kernel(const float* __restrict__ x,
                  const float* __restrict__ dw_w,
                  const float* __restrict__ dw_b,
                  const float* __restrict__ dw_gamma,
                  const float* __restrict__ dw_beta,
                  const float* __restrict__ dw_mean,
                  const float* __restrict__ dw_var,
                  const float* __restrict__ pw_w,
                  const float* __restrict__ pw_b,
                  const float* __restrict__ pw_gamma,
                  const float* __restrict__ pw_beta,
                  const float* __restrict__ pw_mean,
                  const float* __restrict__ pw_var,
                  float* __restrict__ out)
{
    const int map = blockIdx.x;            // b * CIN + c
    const int c   = map & (CIN - 1);
    const int b   = map >> 8;
    const int tid = threadIdx.x;

    const int cp    = tid & 31;            // column pair index, valid < 27
    const int grp   = tid >> 5;            // 0..7
    const int row0  = grp * 7;
    const int nrows = (grp == 7) ? 5 : 7;  // 7*7 + 5 = 54
    const int col   = 2 * cp;
    const bool colok = (cp < 27);

    // ---------- (0) prefetch first two input rows for the conv ----------
    const float2* prow = (const float2*)(x + (size_t)map * (HIN * WIN)
                                           + (size_t)row0 * WIN + col);
    float2 aL, aR, bL, bR;
    if (colok) {
        aL = prow[0]; aR = prow[1]; prow += WIN / 2;
        bL = prow[0]; bR = prow[1]; prow += WIN / 2;
    }

    // ---------- (1) speculative pointwise streaming stores ----------
    {
        const int o0 = 2 * c, o1 = 2 * c + 1;
        const float sc0 = __ldg(pw_gamma + o0) * rsqrtf(__ldg(pw_var + o0) + EPS);
        const float sh0 = __ldg(pw_beta + o0) - __ldg(pw_mean + o0) * sc0;
        float v0 = fmaxf(fmaf(__ldg(pw_b + o0), sc0, sh0), 0.0f);
        if (v0 < PW_THRESH) v0 = 0.0f;
        const float sc1 = __ldg(pw_gamma + o1) * rsqrtf(__ldg(pw_var + o1) + EPS);
        const float sh1 = __ldg(pw_beta + o1) - __ldg(pw_mean + o1) * sc1;
        float v1 = fmaxf(fmaf(__ldg(pw_b + o1), sc1, sh1), 0.0f);
        if (v1 < PW_THRESH) v1 = 0.0f;

        const float4 val0 = make_float4(v0, v0, v0, v0);
        const float4 val1 = make_float4(v1, v1, v1, v1);
        float4* op0 = (float4*)(out + ((size_t)b * COUT + o0) * HWOUT);
        float4* op1 = (float4*)(out + ((size_t)b * COUT + o1) * HWOUT);
        #pragma unroll
        for (int r = 0; r < 3; r++) {
            const int idx = tid + r * 256;
            if (idx < HWOUT / 4) {                     // 729 float4 per map
                __stcs(op0 + idx, val0);
                __stcs(op1 + idx, val1);
            }
        }
    }

    // ---------- (2) depthwise role ----------
    const float w0 = __ldg(dw_w + c * 9 + 0);
    const float w1 = __ldg(dw_w + c * 9 + 1);
    const float w2 = __ldg(dw_w + c * 9 + 2);
    const float w3 = __ldg(dw_w + c * 9 + 3);
    const float w4 = __ldg(dw_w + c * 9 + 4);
    const float w5 = __ldg(dw_w + c * 9 + 5);
    const float w6 = __ldg(dw_w + c * 9 + 6);
    const float w7 = __ldg(dw_w + c * 9 + 7);
    const float w8 = __ldg(dw_w + c * 9 + 8);

    const float scale = __ldg(dw_gamma + c) * rsqrtf(__ldg(dw_var + c) + EPS);
    const float shift = __ldg(dw_beta + c) - __ldg(dw_mean + c) * scale;
    const float bias  = __ldg(dw_b + c);

    float vL[7], vR[7];
    float mx = 0.0f;

    if (colok) {
        #pragma unroll
        for (int r = 0; r < 7; r++) {
            if (r < nrows) {
                const float2 cL = prow[0], cR = prow[1]; prow += WIN / 2;
                float accL = aL.x * w0, accR = aL.y * w0;
                accL = fmaf(aL.y, w1, accL);  accR = fmaf(aR.x, w1, accR);
                accL = fmaf(aR.x, w2, accL);  accR = fmaf(aR.y, w2, accR);
                accL = fmaf(bL.x, w3, accL);  accR = fmaf(bL.y, w3, accR);
                accL = fmaf(bL.y, w4, accL);  accR = fmaf(bR.x, w4, accR);
                accL = fmaf(bR.x, w5, accL);  accR = fmaf(bR.y, w5, accR);
                accL = fmaf(cL.x, w6, accL);  accR = fmaf(cL.y, w6, accR);
                accL = fmaf(cL.y, w7, accL);  accR = fmaf(cR.x, w7, accR);
                accL = fmaf(cR.x, w8, accL);  accR = fmaf(cR.y, w8, accR);
                const float zL = fmaxf(fmaf(accL + bias, scale, shift), 0.0f);
                const float zR = fmaxf(fmaf(accR + bias, scale, shift), 0.0f);
                vL[r] = zL; vR[r] = zR;
                mx = fmaxf(mx, fmaxf(zL, zR));
                aL = bL; aR = bR;
                bL = cL; bR = cR;
            }
        }
    }

    const float bmax = block_max_256(mx);
    const int survive = (bmax >= DW_THRESH) ? 1 : 0;

    if (survive && colok) {
        float* yout = g_y + (size_t)map * HWOUT + col;
        #pragma unroll
        for (int r = 0; r < 7; r++)
            if (r < nrows)
                *(float2*)(yout + (row0 + r) * WOUT) = make_float2(vL[r], vR[r]);
    }
    if (survive) __threadfence();          // publish y (rare path; all threads)

    // ---------- (3) release counting + last-block repair ----------
    __shared__ int s_last;
    __syncthreads();                       // all y stores issued before release
    if (tid == 0) {
        g_flag[map] = survive;
        __threadfence();                   // order flag (and y) before counters
        int last = 0;
        if (atomicAdd(&g_done[b], 1) == CIN - 1) {
            if (atomicAdd(&g_batchdone, 1) == B_ - 1) last = 1;
        }
        s_last = last;
    }
    __syncthreads();

    if (s_last) {
        __threadfence();                   // acquire: see all flags/y
        repair_all(pw_w, pw_b, pw_gamma, pw_beta, pw_mean, pw_var, out);
        __syncthreads();
        if (tid == 0) {                    // self-reset for next graph replay
            #pragma unroll
            for (int i = 0; i < B_; i++) g_done[i] = 0;
            g_batchdone = 0;
        }
    }
}

// ---------------------------------------------------------------------------
extern "C" void kernel_launch(void* const* d_in, const int* in_sizes, int n_in,
                              void* d_out, int out_size)
{
    const float* x        = (const float*)d_in[0];
    const float* dw_w     = (const float*)d_in[1];
    const float* dw_b     = (const float*)d_in[2];
    const float* dw_gamma = (const float*)d_in[3];
    const float* dw_beta  = (const float*)d_in[4];
    const float* dw_mean  = (const float*)d_in[5];
    const float* dw_var   = (const float*)d_in[6];
    const float* pw_w     = (const float*)d_in[7];
    const float* pw_b     = (const float*)d_in[8];
    const float* pw_gamma = (const float*)d_in[9];
    const float* pw_beta  = (const float*)d_in[10];
    const float* pw_mean  = (const float*)d_in[11];
    const float* pw_var   = (const float*)d_in[12];
    float* out = (float*)d_out;

    fused_kernel<<<B_ * CIN, 256>>>(
        x, dw_w, dw_b, dw_gamma, dw_beta, dw_mean, dw_var,
        pw_w, pw_b, pw_gamma, pw_beta, pw_mean, pw_var, out);
}

// round 12
// speedup vs baseline: 1.4477x; 1.4477x over previous
#include <cuda_runtime.h>
#include <cstdint>

#define B_    32
#define CIN   256
#define COUT  512
#define HIN   56
#define WIN   56
#define HOUT  54
#define WOUT  54
#define HWOUT (HOUT * WOUT)          // 2916 = 729 * 4
#define EPS   1e-5f
#define DW_THRESH 4.0f
#define PW_THRESH 0.001f

// Scratch (device globals: the only allowed scratch mechanism).
__device__ float g_y[(size_t)B_ * CIN * HWOUT];   // depthwise output, written only for survivors
__device__ int   g_flag[B_ * CIN];                // per-(b,c) survival flag (rewritten every run)

__device__ __forceinline__ float block_max_256(float v) {
    __shared__ float s_red[8];
    #pragma unroll
    for (int off = 16; off > 0; off >>= 1)
        v = fmaxf(v, __shfl_down_sync(0xffffffffu, v, off));
    if ((threadIdx.x & 31) == 0) s_red[threadIdx.x >> 5] = v;
    __syncthreads();
    if (threadIdx.x < 8) {
        v = s_red[threadIdx.x];
        #pragma unroll
        for (int off = 4; off > 0; off >>= 1)
            v = fmaxf(v, __shfl_down_sync(0xffu, v, off));
        if (threadIdx.x == 0) s_red[0] = v;
    }
    __syncthreads();
    float r = s_red[0];
    __syncthreads();
    return r;
}

// ---------------------------------------------------------------------------
// Fused kernel: 8192 blocks; block (b,c):
//   (0) prefetch first two conv input rows into registers
//   (1) speculative pw streaming stores for output maps (b,2c), (b,2c+1)
//   (2) depthwise conv pass 1: max only (no per-row value arrays -> low regs)
//   (3) rare survivor path: pass 2 recomputes and stores y
// Register-lean so 8 blocks/SM stay resident (max MLP for the mem streams).
// ---------------------------------------------------------------------------
__global__ __launch_bounds__(256, 8)
void fused_kernel(const float* __restrict__ x,
                  const float* __restrict__ dw_w,
                  const float* __restrict__ dw_b,
                  const float* __restrict__ dw_gamma,
                  const float* __restrict__ dw_beta,
                  const float* __restrict__ dw_mean,
                  const float* __restrict__ dw_var,
                  const float* __restrict__ pw_b,
                  const float* __restrict__ pw_gamma,
                  const float* __restrict__ pw_beta,
                  const float* __restrict__ pw_mean,
                  const float* __restrict__ pw_var,
                  float* __restrict__ out)
{
    const int map = blockIdx.x;            // b * CIN + c
    const int c   = map & (CIN - 1);
    const int b   = map >> 8;
    const int tid = threadIdx.x;

    const int cp    = tid & 31;            // column pair index, valid < 27
    const int grp   = tid >> 5;            // 0..7
    const int row0  = grp * 7;
    const int nrows = (grp == 7) ? 5 : 7;  // 7*7 + 5 = 54
    const int col   = 2 * cp;
    const bool colok = (cp < 27);

    // ---------- (0) prefetch first two input rows ----------
    const float2* prow0 = (const float2*)(x + (size_t)map * (HIN * WIN)
                                            + (size_t)row0 * WIN + col);
    const float2* prow = prow0;
    float2 aL, aR, bL, bR;
    if (colok) {
        aL = prow[0]; aR = prow[1]; prow += WIN / 2;
        bL = prow[0]; bR = prow[1]; prow += WIN / 2;
    }

    // ---------- (1) speculative pointwise streaming stores ----------
    {
        const int o0 = 2 * c, o1 = 2 * c + 1;
        const float sc0 = __ldg(pw_gamma + o0) * rsqrtf(__ldg(pw_var + o0) + EPS);
        const float sh0 = __ldg(pw_beta + o0) - __ldg(pw_mean + o0) * sc0;
        float v0 = fmaxf(fmaf(__ldg(pw_b + o0), sc0, sh0), 0.0f);
        if (v0 < PW_THRESH) v0 = 0.0f;
        const float sc1 = __ldg(pw_gamma + o1) * rsqrtf(__ldg(pw_var + o1) + EPS);
        const float sh1 = __ldg(pw_beta + o1) - __ldg(pw_mean + o1) * sc1;
        float v1 = fmaxf(fmaf(__ldg(pw_b + o1), sc1, sh1), 0.0f);
        if (v1 < PW_THRESH) v1 = 0.0f;

        const float4 val0 = make_float4(v0, v0, v0, v0);
        const float4 val1 = make_float4(v1, v1, v1, v1);
        float4* op0 = (float4*)(out + ((size_t)b * COUT + o0) * HWOUT);
        float4* op1 = (float4*)(out + ((size_t)b * COUT + o1) * HWOUT);
        #pragma unroll
        for (int r = 0; r < 3; r++) {
            const int idx = tid + r * 256;
            if (idx < HWOUT / 4) {                     // 729 float4 per map
                __stcs(op0 + idx, val0);
                __stcs(op1 + idx, val1);
            }
        }
    }

    // ---------- (2) depthwise pass 1: max only ----------
    const float w0 = __ldg(dw_w + c * 9 + 0);
    const float w1 = __ldg(dw_w + c * 9 + 1);
    const float w2 = __ldg(dw_w + c * 9 + 2);
    const float w3 = __ldg(dw_w + c * 9 + 3);
    const float w4 = __ldg(dw_w + c * 9 + 4);
    const float w5 = __ldg(dw_w + c * 9 + 5);
    const float w6 = __ldg(dw_w + c * 9 + 6);
    const float w7 = __ldg(dw_w + c * 9 + 7);
    const float w8 = __ldg(dw_w + c * 9 + 8);

    const float scale = __ldg(dw_gamma + c) * rsqrtf(__ldg(dw_var + c) + EPS);
    const float shift = __ldg(dw_beta + c) - __ldg(dw_mean + c) * scale;
    const float bias  = __ldg(dw_b + c);

    float mx = 0.0f;
    if (colok) {
        #pragma unroll
        for (int r = 0; r < 7; r++) {
            if (r < nrows) {
                const float2 cL = prow[0], cR = prow[1]; prow += WIN / 2;
                float accL = aL.x * w0, accR = aL.y * w0;
                accL = fmaf(aL.y, w1, accL);  accR = fmaf(aR.x, w1, accR);
                accL = fmaf(aR.x, w2, accL);  accR = fmaf(aR.y, w2, accR);
                accL = fmaf(bL.x, w3, accL);  accR = fmaf(bL.y, w3, accR);
                accL = fmaf(bL.y, w4, accL);  accR = fmaf(bR.x, w4, accR);
                accL = fmaf(bR.x, w5, accL);  accR = fmaf(bR.y, w5, accR);
                accL = fmaf(cL.x, w6, accL);  accR = fmaf(cL.y, w6, accR);
                accL = fmaf(cL.y, w7, accL);  accR = fmaf(cR.x, w7, accR);
                accL = fmaf(cR.x, w8, accL);  accR = fmaf(cR.y, w8, accR);
                const float zL = fmaxf(fmaf(accL + bias, scale, shift), 0.0f);
                const float zR = fmaxf(fmaf(accR + bias, scale, shift), 0.0f);
                mx = fmaxf(mx, fmaxf(zL, zR));
                aL = bL; aR = bR;
                bL = cL; bR = cR;
            }
        }
    }

    const float bmax = block_max_256(mx);
    const int survive = (bmax >= DW_THRESH) ? 1 : 0;
    if (tid == 0) g_flag[map] = survive;

    // ---------- (3) rare survivor path: pass 2 recompute + store ----------
    if (survive && colok) {
        const float2* p2 = prow0;
        float2 a2L = p2[0], a2R = p2[1]; p2 += WIN / 2;
        float2 b2L = p2[0], b2R = p2[1]; p2 += WIN / 2;
        float* yout = g_y + (size_t)map * HWOUT + col;
        #pragma unroll
        for (int r = 0; r < 7; r++) {
            if (r < nrows) {
                const float2 c2L = p2[0], c2R = p2[1]; p2 += WIN / 2;
                float accL = a2L.x * w0, accR = a2L.y * w0;
                accL = fmaf(a2L.y, w1, accL);  accR = fmaf(a2R.x, w1, accR);
                accL = fmaf(a2R.x, w2, accL);  accR = fmaf(a2R.y, w2, accR);
                accL = fmaf(b2L.x, w3, accL);  accR = fmaf(b2L.y, w3, accR);
                accL = fmaf(b2L.y, w4, accL);  accR = fmaf(b2R.x, w4, accR);
                accL = fmaf(b2R.x, w5, accL);  accR = fmaf(b2R.y, w5, accR);
                accL = fmaf(c2L.x, w6, accL);  accR = fmaf(c2L.y, w6, accR);
                accL = fmaf(c2L.y, w7, accL);  accR = fmaf(c2R.x, w7, accR);
                accL = fmaf(c2R.x, w8, accL);  accR = fmaf(c2R.y, w8, accR);
                const float zL = fmaxf(fmaf(accL + bias, scale, shift), 0.0f);
                const float zR = fmaxf(fmaf(accR + bias, scale, shift), 0.0f);
                *(float2*)(yout + (row0 + r) * WOUT) = make_float2(zL, zR);
                a2L = b2L; a2R = b2R;
                b2L = c2L; b2R = c2R;
            }
        }
    }
}

// ---------------------------------------------------------------------------
// Repair kernel: for batches that DID have dw survivors (rare), recompute the
// pointwise result and overwrite the speculative output. Grid (8, 32):
// each block handles 64 output channels of one batch; early-exits otherwise.
// ---------------------------------------------------------------------------
__global__ __launch_bounds__(256)
void repair_kernel(const float* __restrict__ pw_w,
                   const float* __restrict__ pw_b,
                   const float* __restrict__ pw_gamma,
                   const float* __restrict__ pw_beta,
                   const float* __restrict__ pw_mean,
                   const float* __restrict__ pw_var,
                   float* __restrict__ out)
{
    const int bi  = blockIdx.y;
    const int tid = threadIdx.x;

    const int myflag = g_flag[bi * CIN + tid];
    const int any = __syncthreads_or(myflag);
    if (!any) return;                      // common case: batch was all-zero

    __shared__ float wrow[CIN];
    __shared__ char  fl[CIN];
    fl[tid] = (char)(myflag != 0);

    for (int oo = 0; oo < 64; oo++) {
        const int o = blockIdx.x * 64 + oo;
        __syncthreads();
        wrow[tid] = pw_w[(size_t)o * CIN + tid];
        __syncthreads();

        float4 acc[3];
        #pragma unroll
        for (int r = 0; r < 3; r++) acc[r] = make_float4(0.f, 0.f, 0.f, 0.f);

        for (int k = 0; k < CIN; k++) {
            if (!fl[k]) continue;
            const float wv = wrow[k];
            const float4* yr4 = (const float4*)(g_y + ((size_t)bi * CIN + k) * HWOUT);
            #pragma unroll
            for (int r = 0; r < 3; r++) {
                const int idx = tid + r * 256;
                if (idx < HWOUT / 4) {
                    const float4 yv = yr4[idx];
                    acc[r].x = fmaf(yv.x, wv, acc[r].x);
                    acc[r].y = fmaf(yv.y, wv, acc[r].y);
                    acc[r].z = fmaf(yv.z, wv, acc[r].z);
                    acc[r].w = fmaf(yv.w, wv, acc[r].w);
                }
            }
        }

        const float scale = pw_gamma[o] * rsqrtf(pw_var[o] + EPS);
        const float shift = pw_beta[o] - pw_mean[o] * scale;
        const float bias  = pw_b[o];

        float4 z[3];
        float mx = 0.0f;
        #pragma unroll
        for (int r = 0; r < 3; r++) {
            z[r].x = fmaxf(fmaf(acc[r].x + bias, scale, shift), 0.0f);
            z[r].y = fmaxf(fmaf(acc[r].y + bias, scale, shift), 0.0f);
            z[r].z = fmaxf(fmaf(acc[r].z + bias, scale, shift), 0.0f);
            z[r].w = fmaxf(fmaf(acc[r].w + bias, scale, shift), 0.0f);
            mx = fmaxf(mx, fmaxf(fmaxf(z[r].x, z[r].y), fmaxf(z[r].z, z[r].w)));
        }

        const float bmax = block_max_256(mx);
        const bool cut = (bmax < PW_THRESH);

        float4* op4 = (float4*)(out + ((size_t)bi * COUT + o) * HWOUT);
        #pragma unroll
        for (int r = 0; r < 3; r++) {
            const int idx = tid + r * 256;
            if (idx < HWOUT / 4)
                op4[idx] = cut ? make_float4(0.f, 0.f, 0.f, 0.f) : z[r];
        }
    }
}

// ---------------------------------------------------------------------------
extern "C" void kernel_launch(void* const* d_in, const int* in_sizes, int n_in,
                              void* d_out, int out_size)
{
    const float* x        = (const float*)d_in[0];
    const float* dw_w     = (const float*)d_in[1];
    const float* dw_b     = (const float*)d_in[2];
    const float* dw_gamma = (const float*)d_in[3];
    const float* dw_beta  = (const float*)d_in[4];
    const float* dw_mean  = (const float*)d_in[5];
    const float* dw_var   = (const float*)d_in[6];
    const float* pw_w     = (const float*)d_in[7];
    const float* pw_b     = (const float*)d_in[8];
    const float* pw_gamma = (const float*)d_in[9];
    const float* pw_beta  = (const float*)d_in[10];
    const float* pw_mean  = (const float*)d_in[11];
    const float* pw_var   = (const float*)d_in[12];
    float* out = (float*)d_out;

    fused_kernel<<<B_ * CIN, 256>>>(
        x, dw_w, dw_b, dw_gamma, dw_beta, dw_mean, dw_var,
        pw_b, pw_gamma, pw_beta, pw_mean, pw_var, out);

    dim3 rgrid(8, B_);                     // 256 early-exit repair blocks
    repair_kernel<<<rgrid, 256>>>(pw_w, pw_b, pw_gamma, pw_beta,
                                  pw_mean, pw_var, out);
}